// round 8
// baseline (speedup 1.0000x reference)
#include <cuda_runtime.h>
#include <math.h>

#define NH 2
#define NB 2048
#define NM 64
#define ND 16
#define NREL 32

// Fused kernel: 2048 blocks x 128 threads, one b per block (max TLP).
// Phase A: q[r][j] = sum_i R[r][i][j]*item[i], vectorized relm reads (L2-hot).
// Phase B: quad-split gathers, indices hoisted, passes paired for MLP=4.
__global__ __launch_bounds__(128)
void ripple_fused_kernel(const int* __restrict__ items,
                         const int* __restrict__ heads,
                         const int* __restrict__ rels,
                         const int* __restrict__ tails,
                         const float* __restrict__ ent,
                         const float* __restrict__ relm,
                         float* __restrict__ out)
{
    const int b    = blockIdx.x;
    const int t    = threadIdx.x;      // 0..127
    const int lane = t & 31;
    const int wid  = t >> 5;
    const int sub  = t & 3;            // position within quad
    const int quad = t >> 2;           // 0..31

    __shared__ __align__(16) float  item_s[ND];
    __shared__ __align__(16) float4 q_s[NREL * 4];   // [r*4+jg]
    __shared__ float logit_s[NH * NM];
    __shared__ float td_s[NH * NM];
    __shared__ float red_s[8];

    // ---- Phase A0: item embedding ----
    if (t < ND) item_s[t] = ent[(size_t)items[b] * ND + t];
    __syncthreads();

    // ---- Phase A1: q-precompute; thread t owns (r = t>>2, jg = t&3) ----
    {
        const int r  = t >> 2;
        const int jg = t & 3;
        const float4* relm4 = (const float4*)relm;

        float4 a = make_float4(0.f, 0.f, 0.f, 0.f);
        #pragma unroll
        for (int i = 0; i < ND; i++) {
            float4 Rv = relm4[r * 64 + i * 4 + jg];   // R[r][i][jg*4..+3]
            float s = item_s[i];
            a.x += s * Rv.x; a.y += s * Rv.y; a.z += s * Rv.z; a.w += s * Rv.w;
        }
        q_s[t] = a;    // t == r*4+jg
    }
    __syncthreads();

    const float4* ent4 = (const float4*)ent;
    const float4  iv   = ((const float4*)item_s)[sub];

    // ---- Phase B: hoist all 12 indices, then paired-pass gathers ----
    int hidx[4], ridx[4], tidx[4];
    #pragma unroll
    for (int p = 0; p < 4; p++) {
        const int s    = p * 32 + quad;
        const int hop  = s >> 6;
        const int m    = s & 63;
        const int gidx = hop * (NB * NM) + b * NM + m;
        hidx[p] = heads[gidx];
        ridx[p] = rels[gidx];
        tidx[p] = tails[gidx];
    }

    #pragma unroll
    for (int pp = 0; pp < 2; pp++) {
        const int p0 = pp * 2;
        const int p1 = p0 + 1;

        // 4 global gathers + 2 shared reads issued back-to-back
        float4 hv0 = ent4[(size_t)hidx[p0] * 4 + sub];
        float4 tv0 = ent4[(size_t)tidx[p0] * 4 + sub];
        float4 hv1 = ent4[(size_t)hidx[p1] * 4 + sub];
        float4 tv1 = ent4[(size_t)tidx[p1] * 4 + sub];
        float4 qv0 = q_s[ridx[p0] * 4 + sub];
        float4 qv1 = q_s[ridx[p1] * 4 + sub];

        float pl0 = qv0.x * hv0.x + qv0.y * hv0.y + qv0.z * hv0.z + qv0.w * hv0.w;
        float pt0 = iv.x * tv0.x + iv.y * tv0.y + iv.z * tv0.z + iv.w * tv0.w;
        float pl1 = qv1.x * hv1.x + qv1.y * hv1.y + qv1.z * hv1.z + qv1.w * hv1.w;
        float pt1 = iv.x * tv1.x + iv.y * tv1.y + iv.z * tv1.z + iv.w * tv1.w;

        pl0 += __shfl_xor_sync(0xffffffffu, pl0, 1);
        pl0 += __shfl_xor_sync(0xffffffffu, pl0, 2);
        pt0 += __shfl_xor_sync(0xffffffffu, pt0, 1);
        pt0 += __shfl_xor_sync(0xffffffffu, pt0, 2);
        pl1 += __shfl_xor_sync(0xffffffffu, pl1, 1);
        pl1 += __shfl_xor_sync(0xffffffffu, pl1, 2);
        pt1 += __shfl_xor_sync(0xffffffffu, pt1, 1);
        pt1 += __shfl_xor_sync(0xffffffffu, pt1, 2);

        logit_s[p0 * 32 + quad] = pl0;
        td_s[p0 * 32 + quad]    = pt0;
        logit_s[p1 * 32 + quad] = pl1;
        td_s[p1 * 32 + quad]    = pt1;
    }
    __syncthreads();

    // ---- softmax over 64 slots per hop; thread t owns slot t ----
    const int hop = t >> 6;
    float logit = logit_s[t];
    float td    = td_s[t];

    float mx = logit;
    #pragma unroll
    for (int o = 16; o > 0; o >>= 1)
        mx = fmaxf(mx, __shfl_xor_sync(0xffffffffu, mx, o));
    if (lane == 0) red_s[wid] = mx;
    __syncthreads();
    mx = fmaxf(red_s[hop * 2], red_s[hop * 2 + 1]);

    float e = __expf(logit - mx);
    float sm = e;
    #pragma unroll
    for (int o = 16; o > 0; o >>= 1)
        sm += __shfl_xor_sync(0xffffffffu, sm, o);
    if (lane == 0) red_s[4 + wid] = sm;
    __syncthreads();
    sm = red_s[4 + hop * 2] + red_s[4 + hop * 2 + 1];

    const float pi = e / sm;

    // ---- contribution: pi * (tail . item); block-reduce ----
    float c = pi * td;
    #pragma unroll
    for (int o = 16; o > 0; o >>= 1)
        c += __shfl_xor_sync(0xffffffffu, c, o);
    __syncthreads();                 // protect red_s reuse
    if (lane == 0) red_s[wid] = c;
    __syncthreads();

    if (t == 0) {
        float total = red_s[0] + red_s[1] + red_s[2] + red_s[3];
        out[b] = 1.f / (1.f + __expf(-total));
    }
}

extern "C" void kernel_launch(void* const* d_in, const int* in_sizes, int n_in,
                              void* d_out, int out_size)
{
    const int*   items = (const int*)d_in[0];
    const int*   heads = (const int*)d_in[1];
    const int*   rels  = (const int*)d_in[2];
    const int*   tails = (const int*)d_in[3];
    const float* ent   = (const float*)d_in[4];
    const float* relm  = (const float*)d_in[5];
    float*       out   = (float*)d_out;

    ripple_fused_kernel<<<NB, 128>>>(items, heads, rels, tails, ent, relm, out);
}